// round 6
// baseline (speedup 1.0000x reference)
#include <cuda_runtime.h>
#include <cstdint>

// LMN layer, persistent formulation, round 6:
//   node 1: prologue GEMM  xW = x @ Wxh^T + bh
//   node 2: persistent recurrence (128 CTAs x 256 thr, 1 CTA/SM):
//     phase1: CTAs 0-63:  h = tanh(xW[t] + m@Wmh^T)   (16 cols, 8x8 tiles)
//             CTAs 64-127: c2 = m@Wmm^T               (16 cols)
//     grid_sync
//     phase2: all CTAs:   m' = h@Whm^T + c2 + bm      (8 cols, 8x4 tiles)
//     grid_sync
// Fixes vs round 5:
//   * stage stride 2080 (was 2048 + (kg&1)*32 which OVERLAPPED adjacent
//     groups: odd-kg row 63 aliased even-(kg+1) row 0 -> rel_err 0.17).
//     2080/4 mod 32 = 8 quads keeps adjacent-kg LDS windows bank-disjoint.
//   * reduction buffer stride 65 (odd) -> conflict-free STS (was 32-way).
//   * weight shift pads shrunk (WSH 2/1) to fit smem cap; bank math re-audited.

#define T_STEPS 512
#define DIM     1024
#define STEP    (64 * 1024)
#define OUTS    ((size_t)T_STEPS * STEP)

typedef unsigned long long ull;

__device__ __align__(256) float g_xW[(size_t)T_STEPS * STEP];   // 128 MB
__device__ __align__(256) float g_h [STEP];
__device__ __align__(256) float g_c2[STEP];
__device__ unsigned g_cnt = 0;
__device__ unsigned g_gen = 0;

__device__ __forceinline__ void ffma2(ull& d, ull a, ull b) {
    asm("fma.rn.f32x2 %0, %1, %2, %0;" : "+l"(d) : "l"(a), "l"(b));
}
__device__ __forceinline__ float merge2(ull v) {
    float lo, hi;
    asm("mov.b64 {%0, %1}, %2;" : "=f"(lo), "=f"(hi) : "l"(v));
    return lo + hi;
}

// ---- shared layout (floats) ----
// w1 quad-major: slot(kq,c) = kq*16 + (kq>>4)*2 + c  (c 0..15)  -> 16504 f
// w2 quad-major: slot(kq,c) = kq*8  + (kq>>4)*1 + c  (c 0..7)   -> 8252 f
// stage: per k-group base = kg*2080 (2048 used + 32 gap);
//        elem (b,k4) at base + b*32 + ((k4 ^ (b>>3))<<2)        -> 33248 f
// red (aliases stage): addr = tid*65 + elem  (max 16639 < 33248)
constexpr int W1_F    = 16504;
constexpr int W2_F    = 8252;
constexpr int STAGE_F = 15 * 2080 + 2048;       // 33248

__device__ __forceinline__ int stage_base(int kg) { return kg * 2080; }

// ---------------------------------------------------------------------------
// 64 x (2C) GEMM tile: C[row,col] = sum_k A[row,k] * W[col,k]
// 256 thr = 16 k-groups (KPG=64) x 16 positions (8 row-octs x 2 col-halves).
// Thread tile 8 rows x C cols, f32x2 accumulators, 2 rounds of 32-k staging.
// ---------------------------------------------------------------------------
template<int C, int WQ, int WSH, class Epi>
__device__ __forceinline__ void gemm_core(const float* __restrict__ A,
                                          const float* __restrict__ wq,
                                          float* __restrict__ stage,
                                          Epi epi)
{
    constexpr int BN = 2 * C;
    const int tid = threadIdx.x;
    const int kg  = tid >> 4;
    const int p   = tid & 15;
    const int ro  = p >> 1;                   // rows 8ro..8ro+7
    const int co  = p & 1;                    // cols C*co..C*co+C-1
    const int c0  = C * co;

    ull acc[8][C];
    #pragma unroll
    for (int r = 0; r < 8; ++r)
        #pragma unroll
        for (int c = 0; c < C; ++c) acc[r][c] = 0ull;

    #pragma unroll 1
    for (int rd = 0; rd < 2; ++rd) {
        // stage 32 k's for ALL 16 k-groups: 8192 float4 = 32 per thread.
        // slot = j*256+tid: kgS=slot>>9, bS=(slot>>3)&63, k4S=slot&7.
        // 8 consecutive tids read one 128B line (coalesced LDG); swizzled
        // STS.128 lands on 32 distinct bank-quads per warp.
        #pragma unroll
        for (int j = 0; j < 32; ++j) {
            int slot = j * 256 + tid;
            int kgS  = slot >> 9;
            int bS   = (slot >> 3) & 63;
            int k4S  = slot & 7;
            float4 v = *(const float4*)(A + (size_t)bS * DIM
                                          + (kgS << 6) + (rd << 5) + (k4S << 2));
            *(float4*)(stage + stage_base(kgS) + bS * 32
                             + ((k4S ^ (bS >> 3)) << 2)) = v;
        }
        __syncthreads();

        const float* sb = stage + stage_base(kg) + 8 * ro * 32;
        #pragma unroll
        for (int q = 0; q < 8; ++q) {
            ulonglong2 av[8];
            const int sq = ((q ^ ro) & 7) << 2;
            #pragma unroll
            for (int r = 0; r < 8; ++r)
                av[r] = *(const ulonglong2*)(sb + r * 32 + sq);
            const int kq = (kg << 4) + (rd << 3) + q;
            const float* wb = wq + (size_t)(kq * WQ + kg * WSH + c0) * 4;
            #pragma unroll
            for (int c = 0; c < C; ++c) {
                ulonglong2 wv = *(const ulonglong2*)(wb + c * 4);
                #pragma unroll
                for (int r = 0; r < 8; ++r) {
                    ffma2(acc[r][c], av[r].x, wv.x);
                    ffma2(acc[r][c], av[r].y, wv.y);
                }
            }
        }
        __syncthreads();
    }

    // cross-k-group reduction (red aliases stage; stride 65 = odd ->
    // lane*65 mod 32 = lane -> conflict-free STS.32)
    float* red = stage;
    #pragma unroll
    for (int r = 0; r < 8; ++r)
        #pragma unroll
        for (int c = 0; c < C; ++c)
            red[(size_t)tid * 65 + r * C + c] = merge2(acc[r][c]);
    __syncthreads();

    #pragma unroll
    for (int e = tid; e < 64 * BN; e += 256) {
        int row = e / BN, col = e % BN;
        int pos  = ((row >> 3) << 1) | (col / C);
        int elem = (row & 7) * C + (col % C);
        float s = 0.f;
        #pragma unroll
        for (int k = 0; k < 16; ++k)
            s += red[(size_t)((k << 4) + pos) * 65 + elem];
        epi(row, col, s);
    }
    __syncthreads();
}

// load W (row-major [ncols][1024]) into quad-major smem layout, once
template<int WQ, int WSH>
__device__ __forceinline__ void load_w_quad(float* wq,
                                            const float* __restrict__ W,
                                            int ncols, int tid)
{
    for (int e = tid; e < ncols * DIM; e += 256) {
        int c = e >> 10, k = e & 1023;
        int kq = k >> 2, i = k & 3;
        wq[(kq * WQ + (kq >> 4) * WSH + c) * 4 + i] = W[(size_t)c * DIM + k];
    }
}

// fenced sense-counting grid barrier (128 co-resident CTAs)
__device__ __forceinline__ void grid_sync()
{
    __syncthreads();
    if (threadIdx.x == 0) {
        unsigned gen;
        asm volatile("ld.acquire.gpu.u32 %0, [%1];" : "=r"(gen) : "l"(&g_gen));
        __threadfence();
        unsigned prev = atomicAdd(&g_cnt, 1u);
        if (prev == gridDim.x - 1) {
            g_cnt = 0;
            asm volatile("st.release.gpu.u32 [%0], %1;"
                         :: "l"(&g_gen), "r"(gen + 1) : "memory");
        } else {
            unsigned cur;
            do {
                asm volatile("ld.acquire.gpu.u32 %0, [%1];"
                             : "=r"(cur) : "l"(&g_gen));
            } while (cur == gen);
        }
    }
    __syncthreads();
}

// ------------------------- prologue: xW = x @ Wxh^T + bh -------------------
__global__ void __launch_bounds__(256, 1) prologue_k(const float* __restrict__ x,
                                                     const float* __restrict__ Wxh,
                                                     const float* __restrict__ bh)
{
    extern __shared__ float sm[];
    float* w1    = sm;
    float* stage = sm + W1_F;
    load_w_quad<16, 2>(w1, Wxh + (size_t)blockIdx.x * 16 * DIM, 16, threadIdx.x);
    __syncthreads();
    const int nb = blockIdx.x * 16;
    #pragma unroll 1
    for (int rt = 0; rt < 4; ++rt) {
        int ry = blockIdx.y * 4 + rt;
        const float* A = x + (size_t)ry * 64 * DIM;
        float* orow    = g_xW + (size_t)ry * 64 * DIM;
        gemm_core<8, 16, 2>(A, w1, stage, [&](int row, int col, float s) {
            int n = nb + col;
            orow[(size_t)(row << 10) + n] = s + bh[n];
        });
    }
}

// ------------------------- persistent recurrence ---------------------------
__global__ void __launch_bounds__(256, 1) recur_k(const float* __restrict__ m_prev,
                                                  const float* __restrict__ Whm,
                                                  const float* __restrict__ Wmm,
                                                  const float* __restrict__ Wmh,
                                                  const float* __restrict__ bm,
                                                  float* __restrict__ out)
{
    extern __shared__ float sm[];
    float* w1    = sm;
    float* w2    = sm + W1_F;
    float* stage = sm + W1_F + W2_F;
    const int b = blockIdx.x, tid = threadIdx.x;

    const float* W1 = (b < 64) ? (Wmh + (size_t)b * 16 * DIM)
                               : (Wmm + (size_t)(b - 64) * 16 * DIM);
    load_w_quad<16, 2>(w1, W1, 16, tid);
    load_w_quad<8, 1>(w2, Whm + (size_t)b * 8 * DIM, 8, tid);
    __syncthreads();

    const int nb1   = (b & 63) * 16;
    const int nb2   = b * 8;
    const bool hchk = (b < 64);

    #pragma unroll 1
    for (int t = 0; t < T_STEPS; ++t) {
        const float* A   = t ? (out + (size_t)(t - 1) * STEP) : m_prev;
        const float* xwt = g_xW + (size_t)t * STEP;

        gemm_core<8, 16, 2>(A, w1, stage, [&](int row, int col, float s) {
            int n = (row << 10) + nb1 + col;
            if (hchk) g_h[n] = tanhf(xwt[n] + s);
            else      g_c2[n] = s;
        });
        grid_sync();

        float* ot = out + (size_t)t * STEP;
        gemm_core<4, 8, 1>(g_h, w2, stage, [&](int row, int col, float s) {
            int n = (row << 10) + nb2 + col;
            float v = s + g_c2[n] + bm[nb2 + col];
            ot[n] = v;
            if (t == T_STEPS - 1) out[OUTS + n] = v;   // m_final
        });
        grid_sync();
    }
}

#define PRO_SMEM ((W1_F + STAGE_F) * 4)          // 199008 B
#define PER_SMEM ((W1_F + W2_F + STAGE_F) * 4)   // 232016 B

extern "C" void kernel_launch(void* const* d_in, const int* in_sizes, int n_in,
                              void* d_out, int out_size)
{
    const float* x      = (const float*)d_in[0];
    const float* m_prev = (const float*)d_in[1];
    const float* Wxh    = (const float*)d_in[2];
    const float* Whm    = (const float*)d_in[3];
    const float* Wmm    = (const float*)d_in[4];
    const float* Wmh    = (const float*)d_in[5];
    const float* bh     = (const float*)d_in[6];
    const float* bm     = (const float*)d_in[7];
    float* out = (float*)d_out;

    cudaFuncSetAttribute(prologue_k,
                         cudaFuncAttributeMaxDynamicSharedMemorySize, PRO_SMEM);
    cudaFuncSetAttribute(recur_k,
                         cudaFuncAttributeMaxDynamicSharedMemorySize, PER_SMEM);

    prologue_k<<<dim3(64, 128), 256, PRO_SMEM>>>(x, Wxh, bh);
    recur_k<<<128, 256, PER_SMEM>>>(m_prev, Whm, Wmm, Wmh, bm, out);
}

// round 7
// speedup vs baseline: 1.0368x; 1.0368x over previous
#include <cuda_runtime.h>
#include <cstdint>

// LMN layer, persistent formulation, round 6:
//   node 1: prologue GEMM  xW = x @ Wxh^T + bh
//   node 2: persistent recurrence (128 CTAs x 256 thr, 1 CTA/SM):
//     phase1: CTAs 0-63:  h = tanh(xW[t] + m@Wmh^T)   (16 cols, 8x8 tiles)
//             CTAs 64-127: c2 = m@Wmm^T               (16 cols)
//     grid_sync
//     phase2: all CTAs:   m' = h@Whm^T + c2 + bm      (8 cols, 8x4 tiles)
//     grid_sync
// Fixes vs round 5:
//   * stage stride 2080 (was 2048 + (kg&1)*32 which OVERLAPPED adjacent
//     groups: odd-kg row 63 aliased even-(kg+1) row 0 -> rel_err 0.17).
//     2080/4 mod 32 = 8 quads keeps adjacent-kg LDS windows bank-disjoint.
//   * reduction buffer stride 65 (odd) -> conflict-free STS (was 32-way).
//   * weight shift pads shrunk (WSH 2/1) to fit smem cap; bank math re-audited.

#define T_STEPS 512
#define DIM     1024
#define STEP    (64 * 1024)
#define OUTS    ((size_t)T_STEPS * STEP)

typedef unsigned long long ull;

__device__ __align__(256) float g_xW[(size_t)T_STEPS * STEP];   // 128 MB
__device__ __align__(256) float g_h [STEP];
__device__ __align__(256) float g_c2[STEP];
__device__ unsigned g_cnt = 0;
__device__ unsigned g_gen = 0;

__device__ __forceinline__ void ffma2(ull& d, ull a, ull b) {
    asm("fma.rn.f32x2 %0, %1, %2, %0;" : "+l"(d) : "l"(a), "l"(b));
}
__device__ __forceinline__ float merge2(ull v) {
    float lo, hi;
    asm("mov.b64 {%0, %1}, %2;" : "=f"(lo), "=f"(hi) : "l"(v));
    return lo + hi;
}

// ---- shared layout (floats) ----
// w1 quad-major: slot(kq,c) = kq*16 + (kq>>4)*2 + c  (c 0..15)  -> 16504 f
// w2 quad-major: slot(kq,c) = kq*8  + (kq>>4)*1 + c  (c 0..7)   -> 8252 f
// stage: per k-group base = kg*2080 (2048 used + 32 gap);
//        elem (b,k4) at base + b*32 + ((k4 ^ (b>>3))<<2)        -> 33248 f
// red (aliases stage): addr = tid*65 + elem  (max 16639 < 33248)
constexpr int W1_F    = 16504;
constexpr int W2_F    = 8252;
constexpr int STAGE_F = 15 * 2080 + 2048;       // 33248

__device__ __forceinline__ int stage_base(int kg) { return kg * 2080; }

// ---------------------------------------------------------------------------
// 64 x (2C) GEMM tile: C[row,col] = sum_k A[row,k] * W[col,k]
// 256 thr = 16 k-groups (KPG=64) x 16 positions (8 row-octs x 2 col-halves).
// Thread tile 8 rows x C cols, f32x2 accumulators, 2 rounds of 32-k staging.
// ---------------------------------------------------------------------------
template<int C, int WQ, int WSH, class Epi>
__device__ __forceinline__ void gemm_core(const float* __restrict__ A,
                                          const float* __restrict__ wq,
                                          float* __restrict__ stage,
                                          Epi epi)
{
    constexpr int BN = 2 * C;
    const int tid = threadIdx.x;
    const int kg  = tid >> 4;
    const int p   = tid & 15;
    const int ro  = p >> 1;                   // rows 8ro..8ro+7
    const int co  = p & 1;                    // cols C*co..C*co+C-1
    const int c0  = C * co;

    ull acc[8][C];
    #pragma unroll
    for (int r = 0; r < 8; ++r)
        #pragma unroll
        for (int c = 0; c < C; ++c) acc[r][c] = 0ull;

    #pragma unroll 1
    for (int rd = 0; rd < 2; ++rd) {
        // stage 32 k's for ALL 16 k-groups: 8192 float4 = 32 per thread.
        // slot = j*256+tid: kgS=slot>>9, bS=(slot>>3)&63, k4S=slot&7.
        // 8 consecutive tids read one 128B line (coalesced LDG); swizzled
        // STS.128 lands on 32 distinct bank-quads per warp.
        #pragma unroll
        for (int j = 0; j < 32; ++j) {
            int slot = j * 256 + tid;
            int kgS  = slot >> 9;
            int bS   = (slot >> 3) & 63;
            int k4S  = slot & 7;
            float4 v = *(const float4*)(A + (size_t)bS * DIM
                                          + (kgS << 6) + (rd << 5) + (k4S << 2));
            *(float4*)(stage + stage_base(kgS) + bS * 32
                             + ((k4S ^ (bS >> 3)) << 2)) = v;
        }
        __syncthreads();

        const float* sb = stage + stage_base(kg) + 8 * ro * 32;
        #pragma unroll
        for (int q = 0; q < 8; ++q) {
            ulonglong2 av[8];
            const int sq = ((q ^ ro) & 7) << 2;
            #pragma unroll
            for (int r = 0; r < 8; ++r)
                av[r] = *(const ulonglong2*)(sb + r * 32 + sq);
            const int kq = (kg << 4) + (rd << 3) + q;
            const float* wb = wq + (size_t)(kq * WQ + kg * WSH + c0) * 4;
            #pragma unroll
            for (int c = 0; c < C; ++c) {
                ulonglong2 wv = *(const ulonglong2*)(wb + c * 4);
                #pragma unroll
                for (int r = 0; r < 8; ++r) {
                    ffma2(acc[r][c], av[r].x, wv.x);
                    ffma2(acc[r][c], av[r].y, wv.y);
                }
            }
        }
        __syncthreads();
    }

    // cross-k-group reduction (red aliases stage; stride 65 = odd ->
    // lane*65 mod 32 = lane -> conflict-free STS.32)
    float* red = stage;
    #pragma unroll
    for (int r = 0; r < 8; ++r)
        #pragma unroll
        for (int c = 0; c < C; ++c)
            red[(size_t)tid * 65 + r * C + c] = merge2(acc[r][c]);
    __syncthreads();

    #pragma unroll
    for (int e = tid; e < 64 * BN; e += 256) {
        int row = e / BN, col = e % BN;
        int pos  = ((row >> 3) << 1) | (col / C);
        int elem = (row & 7) * C + (col % C);
        float s = 0.f;
        #pragma unroll
        for (int k = 0; k < 16; ++k)
            s += red[(size_t)((k << 4) + pos) * 65 + elem];
        epi(row, col, s);
    }
    __syncthreads();
}

// load W (row-major [ncols][1024]) into quad-major smem layout, once
template<int WQ, int WSH>
__device__ __forceinline__ void load_w_quad(float* wq,
                                            const float* __restrict__ W,
                                            int ncols, int tid)
{
    for (int e = tid; e < ncols * DIM; e += 256) {
        int c = e >> 10, k = e & 1023;
        int kq = k >> 2, i = k & 3;
        wq[(kq * WQ + (kq >> 4) * WSH + c) * 4 + i] = W[(size_t)c * DIM + k];
    }
}

// fenced sense-counting grid barrier (128 co-resident CTAs)
__device__ __forceinline__ void grid_sync()
{
    __syncthreads();
    if (threadIdx.x == 0) {
        unsigned gen;
        asm volatile("ld.acquire.gpu.u32 %0, [%1];" : "=r"(gen) : "l"(&g_gen));
        __threadfence();
        unsigned prev = atomicAdd(&g_cnt, 1u);
        if (prev == gridDim.x - 1) {
            g_cnt = 0;
            asm volatile("st.release.gpu.u32 [%0], %1;"
                         :: "l"(&g_gen), "r"(gen + 1) : "memory");
        } else {
            unsigned cur;
            do {
                asm volatile("ld.acquire.gpu.u32 %0, [%1];"
                             : "=r"(cur) : "l"(&g_gen));
            } while (cur == gen);
        }
    }
    __syncthreads();
}

// ------------------------- prologue: xW = x @ Wxh^T + bh -------------------
__global__ void __launch_bounds__(256, 1) prologue_k(const float* __restrict__ x,
                                                     const float* __restrict__ Wxh,
                                                     const float* __restrict__ bh)
{
    extern __shared__ float sm[];
    float* w1    = sm;
    float* stage = sm + W1_F;
    load_w_quad<16, 2>(w1, Wxh + (size_t)blockIdx.x * 16 * DIM, 16, threadIdx.x);
    __syncthreads();
    const int nb = blockIdx.x * 16;
    #pragma unroll 1
    for (int rt = 0; rt < 4; ++rt) {
        int ry = blockIdx.y * 4 + rt;
        const float* A = x + (size_t)ry * 64 * DIM;
        float* orow    = g_xW + (size_t)ry * 64 * DIM;
        gemm_core<8, 16, 2>(A, w1, stage, [&](int row, int col, float s) {
            int n = nb + col;
            orow[(size_t)(row << 10) + n] = s + bh[n];
        });
    }
}

// ------------------------- persistent recurrence ---------------------------
__global__ void __launch_bounds__(256, 1) recur_k(const float* __restrict__ m_prev,
                                                  const float* __restrict__ Whm,
                                                  const float* __restrict__ Wmm,
                                                  const float* __restrict__ Wmh,
                                                  const float* __restrict__ bm,
                                                  float* __restrict__ out)
{
    extern __shared__ float sm[];
    float* w1    = sm;
    float* w2    = sm + W1_F;
    float* stage = sm + W1_F + W2_F;
    const int b = blockIdx.x, tid = threadIdx.x;

    const float* W1 = (b < 64) ? (Wmh + (size_t)b * 16 * DIM)
                               : (Wmm + (size_t)(b - 64) * 16 * DIM);
    load_w_quad<16, 2>(w1, W1, 16, tid);
    load_w_quad<8, 1>(w2, Whm + (size_t)b * 8 * DIM, 8, tid);
    __syncthreads();

    const int nb1   = (b & 63) * 16;
    const int nb2   = b * 8;
    const bool hchk = (b < 64);

    #pragma unroll 1
    for (int t = 0; t < T_STEPS; ++t) {
        const float* A   = t ? (out + (size_t)(t - 1) * STEP) : m_prev;
        const float* xwt = g_xW + (size_t)t * STEP;

        gemm_core<8, 16, 2>(A, w1, stage, [&](int row, int col, float s) {
            int n = (row << 10) + nb1 + col;
            if (hchk) g_h[n] = tanhf(xwt[n] + s);
            else      g_c2[n] = s;
        });
        grid_sync();

        float* ot = out + (size_t)t * STEP;
        gemm_core<4, 8, 1>(g_h, w2, stage, [&](int row, int col, float s) {
            int n = (row << 10) + nb2 + col;
            float v = s + g_c2[n] + bm[nb2 + col];
            ot[n] = v;
            if (t == T_STEPS - 1) out[OUTS + n] = v;   // m_final
        });
        grid_sync();
    }
}

#define PRO_SMEM ((W1_F + STAGE_F) * 4)          // 199008 B
#define PER_SMEM ((W1_F + W2_F + STAGE_F) * 4)   // 232016 B

extern "C" void kernel_launch(void* const* d_in, const int* in_sizes, int n_in,
                              void* d_out, int out_size)
{
    const float* x      = (const float*)d_in[0];
    const float* m_prev = (const float*)d_in[1];
    const float* Wxh    = (const float*)d_in[2];
    const float* Whm    = (const float*)d_in[3];
    const float* Wmm    = (const float*)d_in[4];
    const float* Wmh    = (const float*)d_in[5];
    const float* bh     = (const float*)d_in[6];
    const float* bm     = (const float*)d_in[7];
    float* out = (float*)d_out;

    cudaFuncSetAttribute(prologue_k,
                         cudaFuncAttributeMaxDynamicSharedMemorySize, PRO_SMEM);
    cudaFuncSetAttribute(recur_k,
                         cudaFuncAttributeMaxDynamicSharedMemorySize, PER_SMEM);

    prologue_k<<<dim3(64, 128), 256, PRO_SMEM>>>(x, Wxh, bh);
    recur_k<<<128, 256, PER_SMEM>>>(m_prev, Whm, Wmm, Wmh, bm, out);
}

// round 8
// speedup vs baseline: 1.4499x; 1.3984x over previous
#include <cuda_runtime.h>
#include <cstdint>

// LMN layer, round 7: no A-staging. A kept k-major in GLOBAL (L2 broadcast),
// row-pair-packed f32x2 FMA with splatted smem weights.
//   node 1: transpose x   -> g_xT  [t][i][b]
//   node 2: transpose m0  -> g_mT  [k][b]
//   node 3: prologue      -> g_xWT [t][n][b]  (xW = x@Wxh^T + bh, transposed)
//   node 4: persistent recurrence (128 CTAs x 512 thr):
//     phase1: CTAs 0-63:  g_hT = tanh(g_xWT[t] + m@Wmh^T)^T  (16 cols)
//             CTAs 64-127: g_c2T = (m@Wmm^T)^T               (16 cols)
//     grid_sync
//     phase2: all: m' = h@Whm^T + c2 + bm -> g_mT (k-major) + out[t] (row-major)
//     grid_sync

#define T_STEPS 512
#define DIM     1024
#define STEP    (64 * 1024)
#define OUTS    ((size_t)T_STEPS * STEP)

typedef unsigned long long ull;

__device__ __align__(256) float g_xT [(size_t)T_STEPS * STEP];  // [t][i][b]
__device__ __align__(256) float g_xWT[(size_t)T_STEPS * STEP];  // [t][n][b]
__device__ __align__(256) float g_mT [STEP];                    // [k][64]
__device__ __align__(256) float g_hT [STEP];                    // [k][64]
__device__ __align__(256) float g_c2T[STEP];                    // [n][64]
__device__ unsigned g_cnt = 0;
__device__ unsigned g_gen = 0;

__device__ __forceinline__ void ffma2(ull& d, ull a, ull b) {
    asm("fma.rn.f32x2 %0, %1, %2, %0;" : "+l"(d) : "l"(a), "l"(b));
}
__device__ __forceinline__ ull addp(ull a, ull b) {
    ull r; asm("add.rn.f32x2 %0, %1, %2;" : "=l"(r) : "l"(a), "l"(b)); return r;
}
__device__ __forceinline__ ull splat(float x) {
    ull r; asm("mov.b64 %0, {%1, %1};" : "=l"(r) : "f"(x)); return r;
}
__device__ __forceinline__ ull packp(float lo, float hi) {
    ull r; asm("mov.b64 %0, {%1, %2};" : "=l"(r) : "f"(lo), "f"(hi)); return r;
}

// smem layout (floats)
constexpr int W1_F  = 1024 * 20;   // w1T [k][20] (16 cols + pad)  80 KB
constexpr int W2_F  = 1024 * 8;    // w2T [k][8]                   32 KB
constexpr int RED_F = 512 * 18 * 2;// 512 pairs x 18 ull           72 KB
constexpr int TR_F  = 8 * 66;      // out-transpose tile

// ---------------------------------------------------------------------------
// 64 x (4C) GEMM tile: C[row,col] = sum_k A[row,k] * W[col,k].
// AT is k-major [k][64] in GLOBAL. 512 thr = 16 warps = 16 k-groups (64 k).
// Lane: ro = lane>>2 (rows 8ro..+7), cg = lane&3 (cols C*cg..+C-1).
// acc[rp][c] = f32x2 over row pair (8ro+2rp, +1). Cross-kg reduce in smem,
// then epi(col-warp w, rowpair-lane l, f32x2 sum).
// ---------------------------------------------------------------------------
template<int C, int WP, class Epi>
__device__ __forceinline__ void gemm_tile(const float* __restrict__ AT,
                                          const float* __restrict__ wT,
                                          float* __restrict__ redsm,
                                          Epi epi)
{
    const int tid  = threadIdx.x;
    const int kg   = tid >> 5;
    const int lane = tid & 31;
    const int ro   = lane >> 2;
    const int cg   = lane & 3;

    ull acc[4][C];
    #pragma unroll
    for (int rp = 0; rp < 4; ++rp)
        #pragma unroll
        for (int c = 0; c < C; ++c) acc[rp][c] = 0ull;

    const int kb = kg << 6;
    const ulonglong2* Au = (const ulonglong2*)AT;   // 16 ul2 per k-row
    const int ab = 2 * ro;

    ulonglong2 nA0 = Au[(size_t)kb * 16 + ab];
    ulonglong2 nA1 = Au[(size_t)kb * 16 + ab + 1];
    ulonglong2 nB0 = Au[(size_t)(kb + 1) * 16 + ab];
    ulonglong2 nB1 = Au[(size_t)(kb + 1) * 16 + ab + 1];

    #pragma unroll 8
    for (int kc = 0; kc < 32; ++kc) {
        ulonglong2 cA0 = nA0, cA1 = nA1, cB0 = nB0, cB1 = nB1;
        int kn = kb + (((kc + 1) & 31) << 1);       // branchless wrap prefetch
        nA0 = Au[(size_t)kn * 16 + ab];
        nA1 = Au[(size_t)kn * 16 + ab + 1];
        nB0 = Au[(size_t)(kn + 1) * 16 + ab];
        nB1 = Au[(size_t)(kn + 1) * 16 + ab + 1];

        const int k0 = kb + 2 * kc;
        auto fmac = [&](int c, float w, const ulonglong2& x0,
                        const ulonglong2& x1) {
            ull s = splat(w);
            ffma2(acc[0][c], x0.x, s); ffma2(acc[1][c], x0.y, s);
            ffma2(acc[2][c], x1.x, s); ffma2(acc[3][c], x1.y, s);
        };
        if constexpr (C == 4) {
            float4 wa = *(const float4*)(wT + (size_t)k0 * WP + 4 * cg);
            fmac(0, wa.x, cA0, cA1); fmac(1, wa.y, cA0, cA1);
            fmac(2, wa.z, cA0, cA1); fmac(3, wa.w, cA0, cA1);
            float4 wb = *(const float4*)(wT + (size_t)(k0 + 1) * WP + 4 * cg);
            fmac(0, wb.x, cB0, cB1); fmac(1, wb.y, cB0, cB1);
            fmac(2, wb.z, cB0, cB1); fmac(3, wb.w, cB0, cB1);
        } else {
            float2 wa = *(const float2*)(wT + (size_t)k0 * WP + 2 * cg);
            fmac(0, wa.x, cA0, cA1); fmac(1, wa.y, cA0, cA1);
            float2 wb = *(const float2*)(wT + (size_t)(k0 + 1) * WP + 2 * cg);
            fmac(0, wb.x, cB0, cB1); fmac(1, wb.y, cB0, cB1);
        }
    }

    // cross-k-group reduction: pair pi = col*32 + rowpair, 16 kg slots,
    // slot swizzle (kg + 4ro + cg)&15 keeps STS ~2-way conflict-free.
    ull* redu = (ull*)redsm;
    const int slot = (kg + 4 * ro + cg) & 15;
    #pragma unroll
    for (int rp = 0; rp < 4; ++rp)
        #pragma unroll
        for (int c = 0; c < C; ++c) {
            int col = C * cg + c;
            int pi  = col * 32 + 4 * ro + rp;
            redu[(size_t)pi * 18 + slot] = acc[rp][c];
        }
    __syncthreads();

    const int w = tid >> 5, l = tid & 31;
    if (w < 4 * C) {
        const ulonglong2* r2 =
            (const ulonglong2*)(redu + (size_t)(w * 32 + l) * 18);
        ulonglong2 v0 = r2[0], v1 = r2[1], v2 = r2[2], v3 = r2[3];
        ulonglong2 v4 = r2[4], v5 = r2[5], v6 = r2[6], v7 = r2[7];
        ull s = addp(addp(addp(addp(v0.x, v0.y), addp(v1.x, v1.y)),
                          addp(addp(v2.x, v2.y), addp(v3.x, v3.y))),
                     addp(addp(addp(v4.x, v4.y), addp(v5.x, v5.y)),
                          addp(addp(v6.x, v6.y), addp(v7.x, v7.y))));
        epi(w, l, s);
    }
    __syncthreads();
}

// fenced sense-counting grid barrier (128 co-resident CTAs)
__device__ __forceinline__ void grid_sync()
{
    __syncthreads();
    if (threadIdx.x == 0) {
        unsigned gen;
        asm volatile("ld.acquire.gpu.u32 %0, [%1];" : "=r"(gen) : "l"(&g_gen));
        __threadfence();
        unsigned prev = atomicAdd(&g_cnt, 1u);
        if (prev == gridDim.x - 1) {
            g_cnt = 0;
            asm volatile("st.release.gpu.u32 [%0], %1;"
                         :: "l"(&g_gen), "r"(gen + 1) : "memory");
        } else {
            unsigned cur;
            do {
                asm volatile("ld.acquire.gpu.u32 %0, [%1];"
                             : "=r"(cur) : "l"(&g_gen));
            } while (cur == gen);
        }
    }
    __syncthreads();
}

// ---------------- 64x64-tile transpose: dst[t][i][b] = src[t][b][i] ---------
__global__ void __launch_bounds__(256) transpose_k(const float* __restrict__ src,
                                                   float* __restrict__ dst)
{
    __shared__ float sm[64 * 65];
    const int t = blockIdx.y, i0 = blockIdx.x * 64, tid = threadIdx.x;
    const float* s = src + (size_t)t * STEP;
    float* d       = dst + (size_t)t * STEP;
    #pragma unroll
    for (int j = 0; j < 16; ++j) {
        int e = j * 256 + tid, b = e >> 6, i = e & 63;
        sm[b * 65 + i] = s[(size_t)b * DIM + i0 + i];
    }
    __syncthreads();
    #pragma unroll
    for (int j = 0; j < 16; ++j) {
        int e = j * 256 + tid, i = e >> 6, b = e & 63;
        d[(size_t)(i0 + i) * 64 + b] = sm[b * 65 + i];
    }
}

// ---------------- prologue: g_xWT[t] = (x[t] @ Wxh^T + bh)^T ----------------
__global__ void __launch_bounds__(512, 1) prologue_k(const float* __restrict__ Wxh,
                                                     const float* __restrict__ bh)
{
    extern __shared__ float sm[];
    float* w1  = sm;
    float* red = sm + W1_F;
    const int cx = blockIdx.x, tid = threadIdx.x;
    for (int e = tid; e < 16 * DIM; e += 512) {
        int c = e >> 10, k = e & 1023;
        w1[k * 20 + c] = Wxh[(size_t)(cx * 16 + c) * DIM + k];
    }
    __syncthreads();
    const int nb = cx * 16;
    #pragma unroll 1
    for (int i = 0; i < 4; ++i) {
        int t = blockIdx.y * 4 + i;
        const float* AT = g_xT + (size_t)t * STEP;
        float* xo       = g_xWT + (size_t)t * STEP;
        gemm_tile<4, 20>(AT, w1, red, [&](int w, int l, ull s) {
            int n = nb + w;
            *(ull*)(xo + (size_t)n * 64 + 2 * l) = addp(s, splat(bh[n]));
        });
    }
}

// ---------------- persistent recurrence ------------------------------------
__global__ void __launch_bounds__(512, 1) recur_k(const float* __restrict__ Whm,
                                                  const float* __restrict__ Wmm,
                                                  const float* __restrict__ Wmh,
                                                  const float* __restrict__ bm,
                                                  float* __restrict__ out)
{
    extern __shared__ float sm[];
    float* w1   = sm;                       // [k][20]
    float* w2   = sm + W1_F;                // [k][8]
    float* red  = sm + W1_F + W2_F;
    float* trsm = sm + W1_F + W2_F + RED_F; // [8][66]
    const int b = blockIdx.x, tid = threadIdx.x;

    const float* W1 = (b < 64) ? (Wmh + (size_t)b * 16 * DIM)
                               : (Wmm + (size_t)(b - 64) * 16 * DIM);
    for (int e = tid; e < 16 * DIM; e += 512) {
        int c = e >> 10, k = e & 1023;
        w1[k * 20 + c] = W1[(size_t)c * DIM + k];
    }
    for (int e = tid; e < 8 * DIM; e += 512) {
        int c = e >> 10, k = e & 1023;
        w2[k * 8 + c] = Whm[(size_t)b * 8 * DIM + (size_t)c * DIM + k];
    }
    __syncthreads();

    const int nb1 = (b & 63) * 16;
    const int nb2 = b * 8;
    const bool hq = (b < 64);

    #pragma unroll 1
    for (int t = 0; t < T_STEPS; ++t) {
        const float* xwt = g_xWT + (size_t)t * STEP;

        gemm_tile<4, 20>(g_mT, w1, red, [&](int w, int l, ull s) {
            int n = nb1 + w;
            if (hq) {
                ull xw = *(const ull*)(xwt + (size_t)n * 64 + 2 * l);
                ull v  = addp(s, xw);
                float lo = __uint_as_float((unsigned)v);
                float hi = __uint_as_float((unsigned)(v >> 32));
                *(ull*)(g_hT + (size_t)n * 64 + 2 * l) =
                    packp(tanhf(lo), tanhf(hi));
            } else {
                *(ull*)(g_c2T + (size_t)n * 64 + 2 * l) = s;
            }
        });
        grid_sync();

        float* ot = out + (size_t)t * STEP;
        gemm_tile<2, 8>(g_hT, w2, red, [&](int w, int l, ull s) {
            int n = nb2 + w;
            ull c2 = *(const ull*)(g_c2T + (size_t)n * 64 + 2 * l);
            ull v  = addp(addp(s, c2), splat(bm[n]));
            *(ull*)(g_mT + (size_t)n * 64 + 2 * l) = v;     // next step's A
            *(ull*)(trsm + w * 66 + 2 * l) = v;             // for out store
        });
        // gemm_tile's trailing __syncthreads makes trsm visible
        {
            int bb = tid >> 3, c = tid & 7;                 // 512 = 64b x 8c
            float v = trsm[c * 66 + bb];
            ot[(size_t)bb * DIM + nb2 + c] = v;
            if (t == T_STEPS - 1)
                out[OUTS + (size_t)bb * DIM + nb2 + c] = v; // m_final
        }
        grid_sync();
    }
}

#define PRO_SMEM ((W1_F + RED_F) * 4)                   // 155648 B
#define PER_SMEM ((W1_F + W2_F + RED_F + TR_F) * 4)     // 190640 B

extern "C" void kernel_launch(void* const* d_in, const int* in_sizes, int n_in,
                              void* d_out, int out_size)
{
    const float* x      = (const float*)d_in[0];
    const float* m_prev = (const float*)d_in[1];
    const float* Wxh    = (const float*)d_in[2];
    const float* Whm    = (const float*)d_in[3];
    const float* Wmm    = (const float*)d_in[4];
    const float* Wmh    = (const float*)d_in[5];
    const float* bh     = (const float*)d_in[6];
    const float* bm     = (const float*)d_in[7];
    float* out = (float*)d_out;

    cudaFuncSetAttribute(prologue_k,
                         cudaFuncAttributeMaxDynamicSharedMemorySize, PRO_SMEM);
    cudaFuncSetAttribute(recur_k,
                         cudaFuncAttributeMaxDynamicSharedMemorySize, PER_SMEM);

    float* d_gxT; cudaGetSymbolAddress((void**)&d_gxT, g_xT);
    float* d_gmT; cudaGetSymbolAddress((void**)&d_gmT, g_mT);

    transpose_k<<<dim3(16, 512), 256>>>(x, d_gxT);          // x -> g_xT
    transpose_k<<<dim3(16, 1), 256>>>(m_prev, d_gmT);       // m0 -> g_mT
    prologue_k<<<dim3(64, 128), 512, PRO_SMEM>>>(Wxh, bh);
    recur_k<<<128, 512, PER_SMEM>>>(Whm, Wmm, Wmh, bm, out);
}

// round 9
// speedup vs baseline: 1.4591x; 1.0064x over previous
#include <cuda_runtime.h>
#include <cstdint>

// LMN layer, round 9: round-7 structure (A k-major in global, no staging),
// gemm_tile rebuilt for latency coverage:
//   - lanes = 16 row-octs x 2 col-halves (4 rows/thread) -> A operand 1 ul2/k
//   - depth-2 A prefetch (LDG in flight ~2 iters >> L2 latency)
//   - depth-1 weight prefetch (LDS consumed one iter after issue)
//   - buffer rotation via i&1, compute-then-refill (WAR, no copies)
// Graph: transpose x -> g_xT; transpose m0 -> g_mT; prologue -> g_xWT;
//        persistent recur (128 CTAs x 512 thr, 2 phases + 2 grid_syncs/step).

#define T_STEPS 512
#define DIM     1024
#define STEP    (64 * 1024)
#define OUTS    ((size_t)T_STEPS * STEP)

typedef unsigned long long ull;

__device__ __align__(256) float g_xT [(size_t)T_STEPS * STEP];  // [t][i][b]
__device__ __align__(256) float g_xWT[(size_t)T_STEPS * STEP];  // [t][n][b]
__device__ __align__(256) float g_mT [STEP];                    // [k][64]
__device__ __align__(256) float g_hT [STEP];                    // [k][64]
__device__ __align__(256) float g_c2T[STEP];                    // [n][64]
__device__ unsigned g_cnt = 0;
__device__ unsigned g_gen = 0;

__device__ __forceinline__ void ffma2(ull& d, ull a, ull b) {
    asm("fma.rn.f32x2 %0, %1, %2, %0;" : "+l"(d) : "l"(a), "l"(b));
}
__device__ __forceinline__ ull addp(ull a, ull b) {
    ull r; asm("add.rn.f32x2 %0, %1, %2;" : "=l"(r) : "l"(a), "l"(b)); return r;
}
__device__ __forceinline__ ull splat(float x) {
    ull r; asm("mov.b64 %0, {%1, %1};" : "=l"(r) : "f"(x), "f"(x)); return r;
}
__device__ __forceinline__ ull packp(float lo, float hi) {
    ull r; asm("mov.b64 %0, {%1, %2};" : "=l"(r) : "f"(lo), "f"(hi)); return r;
}

// smem layout (floats)
constexpr int W1_F  = 1024 * 20;    // w1T [k][20] (16 cols + pad)   80 KB
constexpr int W2_F  = 1024 * 8;     // w2T [k][8]                    32 KB
constexpr int RED_F = 512 * 18 * 2; // 512 pairs x 18 ull slots      72 KB
constexpr int TR_F  = 8 * 66;       // out-transpose tile

// ---------------------------------------------------------------------------
// 64 x (2C) GEMM tile: C[row,col] = sum_k A[row,k] * W[col,k].
// AT k-major [k][64] in GLOBAL. 512 thr = 16 warps = 16 k-groups (64 k each).
// Lane: ro = lane&15 (rows 4ro..4ro+3), cg = lane>>4 (cols C*cg..C*cg+C-1).
// acc[rp][c] f32x2 over row pair (4ro+2rp, +1). Per iter (2 k):
//   2 LDG.128 (A, issued for iter i+2), C/2 LDS.128 x2k (W, issued for i+1),
//   2*C*2 = 32 FFMA2 (C=8) binding.
// Cross-kg smem reduction, then epi(col-warp w, rowpair-lane l, f32x2 sum).
// ---------------------------------------------------------------------------
template<int C, int WP, class Epi>
__device__ __forceinline__ void gemm_tile(const float* __restrict__ AT,
                                          const float* __restrict__ wT,
                                          float* __restrict__ redsm,
                                          Epi epi)
{
    constexpr int NV = C / 4;                 // float4 per k per lane
    const int tid  = threadIdx.x;
    const int kg   = tid >> 5;
    const int lane = tid & 31;
    const int ro   = lane & 15;
    const int cg   = lane >> 4;
    const int kb   = kg << 6;

    const ulonglong2* Au = (const ulonglong2*)AT;   // 16 ul2 per k-row
    const float* wbase = wT + 4 * NV * cg;          // this cg's col block

    ull acc[2][C];
    #pragma unroll
    for (int rp = 0; rp < 2; ++rp)
        #pragma unroll
        for (int c = 0; c < C; ++c) acc[rp][c] = 0ull;

    // A: depth-2 prefetch buffers (slot = iter&1)
    ulonglong2 aP[2], aQ[2];
    aP[0] = Au[(size_t)(kb + 0) * 16 + ro];
    aQ[0] = Au[(size_t)(kb + 1) * 16 + ro];
    aP[1] = Au[(size_t)(kb + 2) * 16 + ro];
    aQ[1] = Au[(size_t)(kb + 3) * 16 + ro];

    // W: depth-1 prefetch buffer (iter 0)
    float4 wb[2][NV];
    #pragma unroll
    for (int kk = 0; kk < 2; ++kk)
        #pragma unroll
        for (int v = 0; v < NV; ++v)
            wb[kk][v] = *(const float4*)(wbase + (size_t)(kb + kk) * WP + 4 * v);

    #pragma unroll 2
    for (int i = 0; i < 32; ++i) {
        const int ib = i & 1;
        // ---- compute iter i (reads aP[ib], aQ[ib], wb) ----
        #pragma unroll
        for (int kk = 0; kk < 2; ++kk) {
            const ulonglong2 a = kk ? aQ[ib] : aP[ib];
            #pragma unroll
            for (int v = 0; v < NV; ++v) {
                const float4 w4 = wb[kk][v];
                ull s0 = splat(w4.x), s1 = splat(w4.y);
                ull s2 = splat(w4.z), s3 = splat(w4.w);
                ffma2(acc[0][4*v+0], a.x, s0); ffma2(acc[1][4*v+0], a.y, s0);
                ffma2(acc[0][4*v+1], a.x, s1); ffma2(acc[1][4*v+1], a.y, s1);
                ffma2(acc[0][4*v+2], a.x, s2); ffma2(acc[1][4*v+2], a.y, s2);
                ffma2(acc[0][4*v+3], a.x, s3); ffma2(acc[1][4*v+3], a.y, s3);
            }
        }
        // ---- refill: A for iter i+2 (WAR on aP/aQ[ib]), W for iter i+1 ----
        {
            const int kn = kb + (((i + 2) & 31) << 1);
            aP[ib] = Au[(size_t)kn * 16 + ro];
            aQ[ib] = Au[(size_t)(kn + 1) * 16 + ro];
            const int kw = kb + (((i + 1) & 31) << 1);
            #pragma unroll
            for (int kk = 0; kk < 2; ++kk)
                #pragma unroll
                for (int v = 0; v < NV; ++v)
                    wb[kk][v] = *(const float4*)(wbase
                                 + (size_t)(kw + kk) * WP + 4 * v);
        }
    }

    // cross-k-group reduction: pair pi = col*32 + rowpair, 16 kg slots.
    ull* redu = (ull*)redsm;
    const int slot = (kg + ro + cg) & 15;
    #pragma unroll
    for (int rp = 0; rp < 2; ++rp)
        #pragma unroll
        for (int c = 0; c < C; ++c) {
            int pi = (C * cg + c) * 32 + 2 * ro + rp;
            redu[(size_t)pi * 18 + slot] = acc[rp][c];
        }
    __syncthreads();

    const int w = tid >> 5, l = tid & 31;
    if (w < 2 * C) {
        const ulonglong2* r2 =
            (const ulonglong2*)(redu + (size_t)(w * 32 + l) * 18);
        ulonglong2 v0 = r2[0], v1 = r2[1], v2 = r2[2], v3 = r2[3];
        ulonglong2 v4 = r2[4], v5 = r2[5], v6 = r2[6], v7 = r2[7];
        ull s = addp(addp(addp(addp(v0.x, v0.y), addp(v1.x, v1.y)),
                          addp(addp(v2.x, v2.y), addp(v3.x, v3.y))),
                     addp(addp(addp(v4.x, v4.y), addp(v5.x, v5.y)),
                          addp(addp(v6.x, v6.y), addp(v7.x, v7.y))));
        epi(w, l, s);
    }
    __syncthreads();
}

// fenced sense-counting grid barrier (128 co-resident CTAs)
__device__ __forceinline__ void grid_sync()
{
    __syncthreads();
    if (threadIdx.x == 0) {
        unsigned gen;
        asm volatile("ld.acquire.gpu.u32 %0, [%1];" : "=r"(gen) : "l"(&g_gen));
        __threadfence();
        unsigned prev = atomicAdd(&g_cnt, 1u);
        if (prev == gridDim.x - 1) {
            g_cnt = 0;
            asm volatile("st.release.gpu.u32 [%0], %1;"
                         :: "l"(&g_gen), "r"(gen + 1) : "memory");
        } else {
            unsigned cur;
            do {
                asm volatile("ld.acquire.gpu.u32 %0, [%1];"
                             : "=r"(cur) : "l"(&g_gen));
            } while (cur == gen);
        }
    }
    __syncthreads();
}

// ---------------- 64x64-tile transpose: dst[t][i][b] = src[t][b][i] ---------
__global__ void __launch_bounds__(256) transpose_k(const float* __restrict__ src,
                                                   float* __restrict__ dst)
{
    __shared__ float sm[64 * 65];
    const int t = blockIdx.y, i0 = blockIdx.x * 64, tid = threadIdx.x;
    const float* s = src + (size_t)t * STEP;
    float* d       = dst + (size_t)t * STEP;
    #pragma unroll
    for (int j = 0; j < 16; ++j) {
        int e = j * 256 + tid, b = e >> 6, i = e & 63;
        sm[b * 65 + i] = s[(size_t)b * DIM + i0 + i];
    }
    __syncthreads();
    #pragma unroll
    for (int j = 0; j < 16; ++j) {
        int e = j * 256 + tid, i = e >> 6, b = e & 63;
        d[(size_t)(i0 + i) * 64 + b] = sm[b * 65 + i];
    }
}

// ---------------- prologue: g_xWT[t] = (x[t] @ Wxh^T + bh)^T ----------------
__global__ void __launch_bounds__(512, 1) prologue_k(const float* __restrict__ Wxh,
                                                     const float* __restrict__ bh)
{
    extern __shared__ float sm[];
    float* w1  = sm;
    float* red = sm + W1_F;
    const int cx = blockIdx.x, tid = threadIdx.x;
    for (int e = tid; e < 16 * DIM; e += 512) {
        int c = e >> 10, k = e & 1023;
        w1[k * 20 + c] = Wxh[(size_t)(cx * 16 + c) * DIM + k];
    }
    __syncthreads();
    const int nb = cx * 16;
    #pragma unroll 1
    for (int i = 0; i < 4; ++i) {
        int t = blockIdx.y * 4 + i;
        const float* AT = g_xT + (size_t)t * STEP;
        float* xo       = g_xWT + (size_t)t * STEP;
        gemm_tile<8, 20>(AT, w1, red, [&](int w, int l, ull s) {
            int n = nb + w;
            *(ull*)(xo + (size_t)n * 64 + 2 * l) = addp(s, splat(bh[n]));
        });
    }
}

// ---------------- persistent recurrence ------------------------------------
__global__ void __launch_bounds__(512, 1) recur_k(const float* __restrict__ Whm,
                                                  const float* __restrict__ Wmm,
                                                  const float* __restrict__ Wmh,
                                                  const float* __restrict__ bm,
                                                  float* __restrict__ out)
{
    extern __shared__ float sm[];
    float* w1   = sm;                       // [k][20]
    float* w2   = sm + W1_F;                // [k][8]
    float* red  = sm + W1_F + W2_F;
    float* trsm = sm + W1_F + W2_F + RED_F; // [8][66]
    const int b = blockIdx.x, tid = threadIdx.x;

    const float* W1 = (b < 64) ? (Wmh + (size_t)b * 16 * DIM)
                               : (Wmm + (size_t)(b - 64) * 16 * DIM);
    for (int e = tid; e < 16 * DIM; e += 512) {
        int c = e >> 10, k = e & 1023;
        w1[k * 20 + c] = W1[(size_t)c * DIM + k];
    }
    for (int e = tid; e < 8 * DIM; e += 512) {
        int c = e >> 10, k = e & 1023;
        w2[k * 8 + c] = Whm[(size_t)b * 8 * DIM + (size_t)c * DIM + k];
    }
    __syncthreads();

    const int nb1 = (b & 63) * 16;
    const int nb2 = b * 8;
    const bool hq = (b < 64);

    #pragma unroll 1
    for (int t = 0; t < T_STEPS; ++t) {
        const float* xwt = g_xWT + (size_t)t * STEP;

        gemm_tile<8, 20>(g_mT, w1, red, [&](int w, int l, ull s) {
            int n = nb1 + w;
            if (hq) {
                ull xw = *(const ull*)(xwt + (size_t)n * 64 + 2 * l);
                ull v  = addp(s, xw);
                float lo = __uint_as_float((unsigned)v);
                float hi = __uint_as_float((unsigned)(v >> 32));
                *(ull*)(g_hT + (size_t)n * 64 + 2 * l) =
                    packp(tanhf(lo), tanhf(hi));
            } else {
                *(ull*)(g_c2T + (size_t)n * 64 + 2 * l) = s;
            }
        });
        grid_sync();

        float* ot = out + (size_t)t * STEP;
        gemm_tile<4, 8>(g_hT, w2, red, [&](int w, int l, ull s) {
            int n = nb2 + w;
            ull c2 = *(const ull*)(g_c2T + (size_t)n * 64 + 2 * l);
            ull v  = addp(addp(s, c2), splat(bm[n]));
            *(ull*)(g_mT + (size_t)n * 64 + 2 * l) = v;     // next step's A
            *(ull*)(trsm + w * 66 + 2 * l) = v;             // for out store
        });
        // gemm_tile's trailing __syncthreads makes trsm visible
        {
            int bb = tid >> 3, c = tid & 7;                 // 512 = 64b x 8c
            float v = trsm[c * 66 + bb];
            ot[(size_t)bb * DIM + nb2 + c] = v;
            if (t == T_STEPS - 1)
                out[OUTS + (size_t)bb * DIM + nb2 + c] = v; // m_final
        }
        grid_sync();
    }
}

#define PRO_SMEM ((W1_F + RED_F) * 4)                   // 155648 B
#define PER_SMEM ((W1_F + W2_F + RED_F + TR_F) * 4)     // 190640 B

extern "C" void kernel_launch(void* const* d_in, const int* in_sizes, int n_in,
                              void* d_out, int out_size)
{
    const float* x      = (const float*)d_in[0];
    const float* m_prev = (const float*)d_in[1];
    const float* Wxh    = (const float*)d_in[2];
    const float* Whm    = (const float*)d_in[3];
    const float* Wmm    = (const float*)d_in[4];
    const float* Wmh    = (const float*)d_in[5];
    const float* bh     = (const float*)d_in[6];
    const float* bm     = (const float*)d_in[7];
    float* out = (float*)d_out;

    cudaFuncSetAttribute(prologue_k,
                         cudaFuncAttributeMaxDynamicSharedMemorySize, PRO_SMEM);
    cudaFuncSetAttribute(recur_k,
                         cudaFuncAttributeMaxDynamicSharedMemorySize, PER_SMEM);

    float* d_gxT; cudaGetSymbolAddress((void**)&d_gxT, g_xT);
    float* d_gmT; cudaGetSymbolAddress((void**)&d_gmT, g_mT);

    transpose_k<<<dim3(16, 512), 256>>>(x, d_gxT);          // x  -> g_xT
    transpose_k<<<dim3(16, 1), 256>>>(m_prev, d_gmT);       // m0 -> g_mT
    prologue_k<<<dim3(64, 128), 512, PRO_SMEM>>>(Wxh, bh);
    recur_k<<<128, 512, PER_SMEM>>>(Whm, Wmm, Wmh, bm, out);
}